// round 8
// baseline (speedup 1.0000x reference)
#include <cuda_runtime.h>
#include <math.h>
#include <stdint.h>
#include <stddef.h>

#define R_RAYS 1024
static constexpr size_t NPTS = 131072;

constexpr size_t O_Z      = 0;
constexpr size_t O_SDF    = O_Z + NPTS;
constexpr size_t O_ZT     = O_SDF + NPTS;
constexpr size_t O_SDFT   = O_ZT + NPTS;
constexpr size_t O_ZNEW   = O_SDFT + NPTS;
constexpr size_t O_SDFNEW = O_ZNEW + 1024 * 16;
constexpr size_t O_PTS    = O_SDFNEW + 1024 * 16;
constexpr size_t O_DIST   = O_PTS + NPTS * 3;
constexpr size_t O_E      = O_DIST + NPTS;
constexpr size_t O_H0     = O_E + NPTS * 39;
constexpr size_t O_H1     = O_H0 + NPTS * 256;
constexpr size_t O_H2     = O_H1 + NPTS * 256;
constexpr size_t O_H3     = O_H2 + NPTS * 256;
constexpr size_t O_H4     = O_H3 + NPTS * 217;
constexpr size_t O_H5     = O_H4 + NPTS * 256;
constexpr size_t O_H6     = O_H5 + NPTS * 256;
constexpr size_t O_H7     = O_H6 + NPTS * 256;
constexpr size_t O_OUT8   = O_H7 + NPTS * 256;
constexpr size_t O_B0     = O_OUT8 + NPTS * 257;
constexpr size_t O_B1     = O_B0 + NPTS * 265;
constexpr size_t O_GE     = O_B1 + NPTS * 265;
constexpr size_t O_GRAD   = O_GE + NPTS * 39;
constexpr size_t O_ALPHA  = O_GRAD + NPTS * 3;
constexpr size_t O_WT     = O_ALPHA + NPTS;
constexpr size_t O_RGBS   = O_WT + NPTS;

// pre-split weight pools (hi/lo), 12 matrices: sw0..sw8, cw0..cw2
constexpr size_t WSZ[12] = {
    39*256, 256*256, 256*256, 256*217, 256*256, 256*256,
    256*256, 256*256, 256*257, 265*256, 256*256, 256*3
};
constexpr size_t woff(int i) {
    size_t o = 0;
    for (int j = 0; j < i; j++) o += WSZ[j];
    return o;
}
constexpr size_t WTOT = woff(12);
constexpr size_t O_WHI = O_RGBS + NPTS * 3;
constexpr size_t O_WLO = O_WHI + WTOT;
constexpr size_t SCRATCH_TOTAL = O_WLO + WTOT;

__device__ __align__(256) float d_SCRATCH[SCRATCH_TOTAL];

__device__ __forceinline__ float sigmoidf_(float x) { return 1.0f / (1.0f + expf(-x)); }

__device__ __forceinline__ float tf32r(float x) {
    uint32_t u;
    asm("cvt.rna.tf32.f32 %0, %1;" : "=r"(u) : "f"(x));
    return __uint_as_float(u);
}

__device__ __forceinline__ uint32_t s2u(const void* p) {
    return (uint32_t)__cvta_generic_to_shared(p);
}
__device__ __forceinline__ void cpa16(uint32_t d, const void* s, int sz) {
    asm volatile("cp.async.ca.shared.global [%0], [%1], 16, %2;" :: "r"(d), "l"(s), "r"(sz));
}
__device__ __forceinline__ void cpa4(uint32_t d, const void* s, int sz) {
    asm volatile("cp.async.ca.shared.global [%0], [%1], 4, %2;" :: "r"(d), "l"(s), "r"(sz));
}
#define CP_COMMIT() asm volatile("cp.async.commit_group;")
#define CP_WAIT1()  asm volatile("cp.async.wait_group 1;")

// weight split: Whi = tf32(W), Wlo = tf32(W - Whi)
__global__ void k_wsplit(const float* __restrict__ W, float* __restrict__ Whi,
                         float* __restrict__ Wlo, int n)
{
    int i = blockIdx.x * blockDim.x + threadIdx.x;
    if (i >= n) return;
    float w = W[i];
    float h = tf32r(w);
    Whi[i] = h;
    Wlo[i] = tf32r(w - h);
}

// ============================================================================
// TF32x3 tensor-core GEMM, 2-stage cp.async pipeline, kTile=32.
// B operand pre-split into (Bhi, Blo) in global memory (weights only).
// A split hi/lo at fragment-load time. acc += aH*bL + aL*bH + aH*bH.
// TRB=0: B is [K,N] row-major.  TRB=1: B is [N,K] row-major (C = A @ B^T)
// EPI: 0 linear, 1 softplus(100x)/100, 2 relu, 3 multiply by -expm1(-100*Hm)
// ============================================================================
template <int EPI, int TRB>
__global__ void __launch_bounds__(256) gemm_tc(
    const float* __restrict__ A,
    const float* __restrict__ Bhi, const float* __restrict__ Blo,
    const float* __restrict__ bias, const float* __restrict__ Hm,
    float* __restrict__ C, int M, int N, int K)
{
    extern __shared__ float sm[];
    constexpr int AP = 36;
    constexpr int BP = TRB ? 36 : 136;
    constexpr int A_TILE = 128 * AP;
    constexpr int B_TILE = TRB ? (128 * 36) : (32 * 136);
    float* As0  = sm;
    float* As1  = sm + A_TILE;
    float* BsH0 = sm + 2 * A_TILE;
    float* BsH1 = BsH0 + B_TILE;
    float* BsL0 = BsH1 + B_TILE;
    float* BsL1 = BsL0 + B_TILE;

    const int tid  = threadIdx.x;
    const int wid  = tid >> 5;
    const int lane = tid & 31;
    const int wm = wid & 3;
    const int wn = wid >> 2;
    const int m0 = blockIdx.y * 128;
    const int n0 = blockIdx.x * 128;
    const int r  = lane >> 2;
    const int cq = lane & 3;
    const bool alA = (K & 3) == 0;
    const bool alB = TRB ? alA : ((N & 3) == 0);

    float acc[2][8][4] = {};

    const int nsteps = (K + 31) >> 5;

    auto load_stage = [&](float* Asx, float* BHx, float* BLx, int k0) {
        // ---- A: 128 rows x 32 k
        {
            int row = tid >> 1;
            int c0  = (tid & 1) * 16;
            int gm  = m0 + row;
            const float* src = A + ((gm < M) ? ((size_t)gm * K + k0 + c0) : 0);
            float* dst = Asx + row * AP + c0;
            if (alA) {
#pragma unroll
                for (int c = 0; c < 16; c += 4) {
                    int rem = (gm < M) ? (K - (k0 + c0 + c)) : 0;
                    rem = rem > 4 ? 4 : (rem < 0 ? 0 : rem);
                    cpa16(s2u(dst + c), src + c, rem * 4);
                }
            } else {
#pragma unroll
                for (int c = 0; c < 16; c++) {
                    int ok = (gm < M && (k0 + c0 + c) < K) ? 4 : 0;
                    cpa4(s2u(dst + c), src + c, ok);
                }
            }
        }
        // ---- B hi & lo
        if (TRB == 0) {
            int kk = tid >> 3;
            int c0 = (tid & 7) * 16;
            int gk = k0 + kk;
            size_t so = (gk < K) ? ((size_t)gk * N + n0 + c0) : 0;
            const float* srcH = Bhi + so;
            const float* srcL = Blo + so;
            float* dstH = BHx + kk * BP + c0;
            float* dstL = BLx + kk * BP + c0;
            if (alB) {
#pragma unroll
                for (int c = 0; c < 16; c += 4) {
                    int rem = (gk < K) ? (N - (n0 + c0 + c)) : 0;
                    rem = rem > 4 ? 4 : (rem < 0 ? 0 : rem);
                    cpa16(s2u(dstH + c), srcH + c, rem * 4);
                    cpa16(s2u(dstL + c), srcL + c, rem * 4);
                }
            } else {
#pragma unroll
                for (int c = 0; c < 16; c++) {
                    int ok = (gk < K && (n0 + c0 + c) < N) ? 4 : 0;
                    cpa4(s2u(dstH + c), srcH + c, ok);
                    cpa4(s2u(dstL + c), srcL + c, ok);
                }
            }
        } else {
            int nn = tid >> 1;
            int c0 = (tid & 1) * 16;
            int gn = n0 + nn;
            size_t so = (gn < N) ? ((size_t)gn * K + k0 + c0) : 0;
            const float* srcH = Bhi + so;
            const float* srcL = Blo + so;
            float* dstH = BHx + nn * BP + c0;
            float* dstL = BLx + nn * BP + c0;
            if (alB) {
#pragma unroll
                for (int c = 0; c < 16; c += 4) {
                    int rem = (gn < N) ? (K - (k0 + c0 + c)) : 0;
                    rem = rem > 4 ? 4 : (rem < 0 ? 0 : rem);
                    cpa16(s2u(dstH + c), srcH + c, rem * 4);
                    cpa16(s2u(dstL + c), srcL + c, rem * 4);
                }
            } else {
#pragma unroll
                for (int c = 0; c < 16; c++) {
                    int ok = (gn < N && (k0 + c0 + c) < K) ? 4 : 0;
                    cpa4(s2u(dstH + c), srcH + c, ok);
                    cpa4(s2u(dstL + c), srcL + c, ok);
                }
            }
        }
    };

    load_stage(As0, BsH0, BsL0, 0);
    CP_COMMIT();

    for (int s = 0; s < nsteps; s++) {
        if (s + 1 < nsteps)
            load_stage(((s + 1) & 1) ? As1 : As0,
                       ((s + 1) & 1) ? BsH1 : BsH0,
                       ((s + 1) & 1) ? BsL1 : BsL0, (s + 1) * 32);
        CP_COMMIT();
        CP_WAIT1();
        __syncthreads();

        const float* Ast = (s & 1) ? As1 : As0;
        const float* BHt = (s & 1) ? BsH1 : BsH0;
        const float* BLt = (s & 1) ? BsL1 : BsL0;

#pragma unroll
        for (int k8 = 0; k8 < 32; k8 += 8) {
            uint32_t aH[2][4], aL[2][4];
#pragma unroll
            for (int i = 0; i < 2; i++) {
                int rb = wm * 32 + i * 16 + r;
                float a0 = Ast[rb * AP + k8 + cq];
                float a1 = Ast[(rb + 8) * AP + k8 + cq];
                float a2 = Ast[rb * AP + k8 + cq + 4];
                float a3 = Ast[(rb + 8) * AP + k8 + cq + 4];
                float h;
                h = tf32r(a0); aH[i][0] = __float_as_uint(h); aL[i][0] = __float_as_uint(tf32r(a0 - h));
                h = tf32r(a1); aH[i][1] = __float_as_uint(h); aL[i][1] = __float_as_uint(tf32r(a1 - h));
                h = tf32r(a2); aH[i][2] = __float_as_uint(h); aL[i][2] = __float_as_uint(tf32r(a2 - h));
                h = tf32r(a3); aH[i][3] = __float_as_uint(h); aL[i][3] = __float_as_uint(tf32r(a3 - h));
            }
#pragma unroll
            for (int j = 0; j < 8; j++) {
                int cb = wn * 64 + j * 8 + r;
                uint32_t bH0, bH1, bL0, bL1;
                if (TRB) {
                    bH0 = __float_as_uint(BHt[cb * BP + k8 + cq]);
                    bH1 = __float_as_uint(BHt[cb * BP + k8 + cq + 4]);
                    bL0 = __float_as_uint(BLt[cb * BP + k8 + cq]);
                    bL1 = __float_as_uint(BLt[cb * BP + k8 + cq + 4]);
                } else {
                    bH0 = __float_as_uint(BHt[(k8 + cq) * BP + cb]);
                    bH1 = __float_as_uint(BHt[(k8 + cq + 4) * BP + cb]);
                    bL0 = __float_as_uint(BLt[(k8 + cq) * BP + cb]);
                    bL1 = __float_as_uint(BLt[(k8 + cq + 4) * BP + cb]);
                }
#pragma unroll
                for (int i = 0; i < 2; i++) {
                    asm volatile(
                        "mma.sync.aligned.m16n8k8.row.col.f32.tf32.tf32.f32 "
                        "{%0,%1,%2,%3}, {%4,%5,%6,%7}, {%8,%9}, {%0,%1,%2,%3};"
                        : "+f"(acc[i][j][0]), "+f"(acc[i][j][1]),
                          "+f"(acc[i][j][2]), "+f"(acc[i][j][3])
                        : "r"(aH[i][0]), "r"(aH[i][1]), "r"(aH[i][2]), "r"(aH[i][3]),
                          "r"(bL0), "r"(bL1));
                    asm volatile(
                        "mma.sync.aligned.m16n8k8.row.col.f32.tf32.tf32.f32 "
                        "{%0,%1,%2,%3}, {%4,%5,%6,%7}, {%8,%9}, {%0,%1,%2,%3};"
                        : "+f"(acc[i][j][0]), "+f"(acc[i][j][1]),
                          "+f"(acc[i][j][2]), "+f"(acc[i][j][3])
                        : "r"(aL[i][0]), "r"(aL[i][1]), "r"(aL[i][2]), "r"(aL[i][3]),
                          "r"(bH0), "r"(bH1));
                    asm volatile(
                        "mma.sync.aligned.m16n8k8.row.col.f32.tf32.tf32.f32 "
                        "{%0,%1,%2,%3}, {%4,%5,%6,%7}, {%8,%9}, {%0,%1,%2,%3};"
                        : "+f"(acc[i][j][0]), "+f"(acc[i][j][1]),
                          "+f"(acc[i][j][2]), "+f"(acc[i][j][3])
                        : "r"(aH[i][0]), "r"(aH[i][1]), "r"(aH[i][2]), "r"(aH[i][3]),
                          "r"(bH0), "r"(bH1));
                }
            }
        }
        __syncthreads();
    }

    // ---- epilogue
#pragma unroll
    for (int i = 0; i < 2; i++) {
        int row0 = m0 + wm * 32 + i * 16 + r;
#pragma unroll
        for (int j = 0; j < 8; j++) {
            int col0 = n0 + wn * 64 + j * 8 + cq * 2;
#pragma unroll
            for (int t = 0; t < 4; t++) {
                int row = row0 + (t >> 1) * 8;
                int col = col0 + (t & 1);
                if (row < M && col < N) {
                    float v = acc[i][j][t];
                    if (bias) v += bias[col];
                    if (EPI == 1) {
                        float s = 100.0f * v;
                        v = (fmaxf(s, 0.0f) + log1pf(expf(-fabsf(s)))) * 0.01f;
                    } else if (EPI == 2) {
                        v = fmaxf(v, 0.0f);
                    } else if (EPI == 3) {
                        v = v * (-expm1f(-100.0f * Hm[(size_t)row * N + col]));
                    }
                    C[(size_t)row * N + col] = v;
                }
            }
        }
    }
}

// ===================== small kernels =====================

__global__ void k_ray_init(const float* __restrict__ ro, const float* __restrict__ rd,
                           float* __restrict__ Z)
{
    int r = blockIdx.x * blockDim.x + threadIdx.x;
    if (r >= R_RAYS) return;
    float ox = ro[r*3], oy = ro[r*3+1], oz = ro[r*3+2];
    float dx = rd[r*3], dy = rd[r*3+1], dz = rd[r*3+2];
    float a = dx*dx + dy*dy + dz*dz;
    float b = 2.0f * (ox*dx + oy*dy + oz*dz);
    float mid = -b / (2.0f * a);
    float nv = fmaxf(mid - 1.0f, 0.05f);
    float fv = mid + 1.0f;
    for (int s = 0; s < 64; s++)
        Z[r*64 + s] = nv + (fv - nv) * ((float)s * (1.0f/63.0f));
}

__global__ void k_pts(const float* __restrict__ Z, const float* __restrict__ ro,
                      const float* __restrict__ rd, float* __restrict__ P, int S, int M)
{
    int m = blockIdx.x * blockDim.x + threadIdx.x;
    if (m >= M) return;
    int r = m / S;
    float z = Z[m];
#pragma unroll
    for (int j = 0; j < 3; j++)
        P[(size_t)m*3 + j] = fmaf(rd[r*3+j], z, ro[r*3+j]);
}

__global__ void k_dist_mid_pts(const float* __restrict__ Z, const float* __restrict__ ro,
                               const float* __restrict__ rd, float* __restrict__ P,
                               float* __restrict__ D)
{
    int m = blockIdx.x * blockDim.x + threadIdx.x;
    if (m >= (int)NPTS) return;
    int s = m & 127, r = m >> 7;
    float z = Z[m];
    float d = (s < 127) ? (Z[m+1] - z) : 0.03125f;
    D[m] = d;
    float mz = fmaf(0.5f, d, z);
#pragma unroll
    for (int j = 0; j < 3; j++)
        P[(size_t)m*3 + j] = fmaf(rd[r*3+j], mz, ro[r*3+j]);
}

__global__ void k_embed(const float* __restrict__ P, float* __restrict__ E, int M)
{
    int m = blockIdx.x * blockDim.x + threadIdx.x;
    if (m >= M) return;
    float p0 = P[(size_t)m*3], p1 = P[(size_t)m*3+1], p2 = P[(size_t)m*3+2];
    float* e = E + (size_t)m*39;
    e[0] = p0; e[1] = p1; e[2] = p2;
    float f = 1.0f;
#pragma unroll
    for (int k = 0; k < 6; k++) {
        float s0,c0,s1,c1,s2,c2;
        sincosf(f*p0,&s0,&c0); sincosf(f*p1,&s1,&c1); sincosf(f*p2,&s2,&c2);
        e[3+6*k+0]=s0; e[3+6*k+1]=s1; e[3+6*k+2]=s2;
        e[3+6*k+3]=c0; e[3+6*k+4]=c1; e[3+6*k+5]=c2;
        f *= 2.0f;
    }
}

__global__ void k_concat(const float* __restrict__ H3, const float* __restrict__ E,
                         float* __restrict__ O, int M)
{
    int idx = blockIdx.x * blockDim.x + threadIdx.x;
    if (idx >= M * 256) return;
    int m = idx >> 8, c = idx & 255;
    float v = (c < 217) ? H3[(size_t)m*217 + c] : E[(size_t)m*39 + (c-217)];
    O[idx] = v * 0.7071067811865476f;
}

__global__ void k_sdf_head(const float* __restrict__ H, const float* __restrict__ W8,
                           const float* __restrict__ b8, float* __restrict__ out, int M)
{
    int gw = (blockIdx.x * blockDim.x + threadIdx.x) >> 5;
    int lane = threadIdx.x & 31;
    if (gw >= M) return;
    const float* h = H + (size_t)gw * 256;
    float s = 0.0f;
#pragma unroll
    for (int k = lane; k < 256; k += 32) s = fmaf(h[k], W8[(size_t)k*257], s);
#pragma unroll
    for (int o = 16; o; o >>= 1) s += __shfl_xor_sync(0xffffffffu, s, o);
    if (!lane) out[gw] = s + b8[0];
}

__global__ void k_upsample(const float* __restrict__ ro, const float* __restrict__ rd,
                           const float* __restrict__ Z, const float* __restrict__ SD,
                           float* __restrict__ ZN, int S, float inv_s)
{
    int r = blockIdx.x * blockDim.x + threadIdx.x;
    if (r >= R_RAYS) return;
    float ox = ro[r*3], oy = ro[r*3+1], oz = ro[r*3+2];
    float dx = rd[r*3], dy = rd[r*3+1], dz = rd[r*3+2];
    const float* zr = Z + (size_t)r * S;
    const float* sr = SD + (size_t)r * S;

    float w[128], cdf[129];
    float prev_raw = 0.0f, T = 1.0f, wsum = 0.0f;
    float z_i = zr[0];
    float px = fmaf(dx,z_i,ox), py = fmaf(dy,z_i,oy), pz = fmaf(dz,z_i,oz);
    float rad_i = sqrtf(px*px + py*py + pz*pz);
    float sdf_i = sr[0];

    for (int i = 0; i < S - 1; i++) {
        float z_n = zr[i+1], sdf_n = sr[i+1];
        float qx = fmaf(dx,z_n,ox), qy = fmaf(dy,z_n,oy), qz = fmaf(dz,z_n,oz);
        float rad_n = sqrtf(qx*qx + qy*qy + qz*qz);
        bool inside = (rad_i < 1.0f) || (rad_n < 1.0f);
        float mid_sdf = 0.5f * (sdf_i + sdf_n);
        float raw = (sdf_n - sdf_i) / (z_n - z_i + 1e-5f);
        float cosv = fminf(raw, prev_raw);
        prev_raw = raw;
        cosv = fminf(fmaxf(cosv, -1000.0f), 0.0f);
        if (!inside) cosv = 0.0f;
        float dist = z_n - z_i;
        float pc = sigmoidf_((mid_sdf - cosv*dist*0.5f) * inv_s);
        float nc = sigmoidf_((mid_sdf + cosv*dist*0.5f) * inv_s);
        float alpha = (pc - nc + 1e-5f) / (pc + 1e-5f);
        float wi = alpha * T;
        T *= (1.0f - alpha + 1e-7f);
        wi += 1e-5f;
        w[i] = wi; wsum += wi;
        z_i = z_n; rad_i = rad_n; sdf_i = sdf_n;
    }

    cdf[0] = 0.0f;
    float invsum = 1.0f / wsum;
    for (int i = 0; i < S - 1; i++) cdf[i+1] = cdf[i] + w[i] * invsum;

    for (int j = 0; j < 16; j++) {
        float u = 0.03125f + (float)j * 0.0625f;
        int lo = 0, hi = S;
        while (lo < hi) { int md = (lo + hi) >> 1; if (cdf[md] <= u) lo = md + 1; else hi = md; }
        int below = lo - 1; if (below < 0) below = 0; if (below > S-1) below = S-1;
        int above = lo;     if (above > S-1) above = S-1;
        float c0 = cdf[below], c1 = cdf[above];
        float b0 = zr[below],  b1 = zr[above];
        float den = (c1 - c0) < 1e-5f ? 1.0f : (c1 - c0);
        ZN[r*16 + j] = b0 + (u - c0) / den * (b1 - b0);
    }
}

__global__ void k_merge(const float* __restrict__ Z, const float* __restrict__ SD,
                        const float* __restrict__ ZN, const float* __restrict__ SN,
                        float* __restrict__ ZT, float* __restrict__ ST, int S)
{
    int r = blockIdx.x * blockDim.x + threadIdx.x;
    if (r >= R_RAYS) return;
    const float* zo = Z + (size_t)r*S;  const float* so = SD + (size_t)r*S;
    const float* zn = ZN + r*16;        const float* sn = SN + r*16;
    float* zt = ZT + (size_t)r*(S+16);  float* st = ST + (size_t)r*(S+16);
    int i = 0, j = 0;
    for (int k = 0; k < S + 16; k++) {
        bool useOld = (i < S) && ((j >= 16) || (zo[i] <= zn[j]));
        if (useOld) { zt[k] = zo[i]; st[k] = so[i]; i++; }
        else        { zt[k] = zn[j]; st[k] = sn[j]; j++; }
    }
}

__global__ void k_copy(float* __restrict__ dst, const float* __restrict__ src, int n)
{
    int i = blockIdx.x * blockDim.x + threadIdx.x;
    if (i < n) dst[i] = src[i];
}

__global__ void k_bwinit(const float* __restrict__ H7, const float* __restrict__ W8,
                         float* __restrict__ G, int M)
{
    int idx = blockIdx.x * blockDim.x + threadIdx.x;
    if (idx >= M * 256) return;
    int c = idx & 255;
    G[idx] = W8[(size_t)c * 257] * (-expm1f(-100.0f * H7[idx]));
}

__global__ void k_split(const float* __restrict__ Gin4, const float* __restrict__ H3,
                        float* __restrict__ Gz3, float* __restrict__ GE, int M)
{
    int idx = blockIdx.x * blockDim.x + threadIdx.x;
    if (idx >= M * 256) return;
    int m = idx >> 8, c = idx & 255;
    float v = Gin4[idx] * 0.7071067811865476f;
    if (c < 217)
        Gz3[(size_t)m*217 + c] = v * (-expm1f(-100.0f * H3[(size_t)m*217 + c]));
    else
        GE[(size_t)m*39 + (c - 217)] = v;
}

__global__ void k_gradpts(const float* __restrict__ GEm, const float* __restrict__ GEs,
                          const float* __restrict__ P, float* __restrict__ GR, int M)
{
    int m = blockIdx.x * blockDim.x + threadIdx.x;
    if (m >= M) return;
    const float* ga = GEm + (size_t)m*39;
    const float* gb = GEs + (size_t)m*39;
    float p[3] = {P[(size_t)m*3], P[(size_t)m*3+1], P[(size_t)m*3+2]};
    float g[3];
#pragma unroll
    for (int j = 0; j < 3; j++) g[j] = ga[j] + gb[j];
    float f = 1.0f;
#pragma unroll
    for (int k = 0; k < 6; k++) {
#pragma unroll
        for (int j = 0; j < 3; j++) {
            float s, c;
            sincosf(f * p[j], &s, &c);
            float gs = ga[3+6*k+j]   + gb[3+6*k+j];
            float gc = ga[3+6*k+3+j] + gb[3+6*k+3+j];
            g[j] = fmaf( f * c, gs, g[j]);
            g[j] = fmaf(-f * s, gc, g[j]);
        }
        f *= 2.0f;
    }
#pragma unroll
    for (int j = 0; j < 3; j++) GR[(size_t)m*3 + j] = g[j];
}

__global__ void k_alpha(const float* __restrict__ OUT8, const float* __restrict__ GR,
                        const float* __restrict__ D, const float* __restrict__ rd,
                        const float* __restrict__ var, float* __restrict__ A, int M)
{
    int m = blockIdx.x * blockDim.x + threadIdx.x;
    if (m >= M) return;
    int r = m >> 7;
    float tc = rd[r*3]*GR[(size_t)m*3] + rd[r*3+1]*GR[(size_t)m*3+1] + rd[r*3+2]*GR[(size_t)m*3+2];
    float ic = fminf(tc, 0.0f);
    float sdf = OUT8[(size_t)m * 257];
    float dist = D[m];
    float inv_s = fminf(fmaxf(expf(10.0f * var[0]), 1e-6f), 1e6f);
    float pc = sigmoidf_((sdf - ic*dist*0.5f) * inv_s);
    float nc = sigmoidf_((sdf + ic*dist*0.5f) * inv_s);
    float a = (pc - nc + 1e-5f) / (pc + 1e-5f);
    A[m] = fminf(fmaxf(a, 0.0f), 1.0f);
}

__global__ void k_ray_weights(const float* __restrict__ A, float* __restrict__ W)
{
    int r = blockIdx.x * blockDim.x + threadIdx.x;
    if (r >= R_RAYS) return;
    float T = 1.0f;
    for (int s = 0; s < 128; s++) {
        int m = r*128 + s;
        float a = A[m];
        W[m] = a * T;
        T *= (1.0f - a + 1e-7f);
    }
}

__global__ void k_cin(const float* __restrict__ P, const float* __restrict__ rd,
                      const float* __restrict__ GR, const float* __restrict__ OUT8,
                      float* __restrict__ CIN, int M)
{
    int idx = blockIdx.x * blockDim.x + threadIdx.x;
    if (idx >= M * 265) return;
    int m = idx / 265, c = idx % 265;
    float v;
    if (c < 3) v = P[(size_t)m*3 + c];
    else if (c < 6) { int r = m >> 7; v = rd[r*3 + (c-3)]; }
    else if (c < 9) {
        float g0 = GR[(size_t)m*3], g1 = GR[(size_t)m*3+1], g2 = GR[(size_t)m*3+2];
        float n = fmaxf(sqrtf(g0*g0 + g1*g1 + g2*g2), 1e-6f);
        v = GR[(size_t)m*3 + (c-6)] / n;
    } else v = OUT8[(size_t)m*257 + 1 + (c-9)];
    CIN[idx] = v;
}

__global__ void k_color_head(const float* __restrict__ H, const float* __restrict__ W,
                             const float* __restrict__ b, float* __restrict__ rgbs, int M)
{
    int gw = (blockIdx.x * blockDim.x + threadIdx.x) >> 5;
    int lane = threadIdx.x & 31;
    if (gw >= M) return;
    const float* h = H + (size_t)gw * 256;
    float a0 = 0.f, a1 = 0.f, a2 = 0.f;
#pragma unroll
    for (int k = lane; k < 256; k += 32) {
        float hv = h[k];
        a0 = fmaf(hv, W[k*3+0], a0);
        a1 = fmaf(hv, W[k*3+1], a1);
        a2 = fmaf(hv, W[k*3+2], a2);
    }
#pragma unroll
    for (int o = 16; o; o >>= 1) {
        a0 += __shfl_xor_sync(0xffffffffu, a0, o);
        a1 += __shfl_xor_sync(0xffffffffu, a1, o);
        a2 += __shfl_xor_sync(0xffffffffu, a2, o);
    }
    if (!lane) {
        rgbs[(size_t)gw*3+0] = sigmoidf_(a0 + b[0]);
        rgbs[(size_t)gw*3+1] = sigmoidf_(a1 + b[1]);
        rgbs[(size_t)gw*3+2] = sigmoidf_(a2 + b[2]);
    }
}

__global__ void k_reduce(const float* __restrict__ W, const float* __restrict__ rgbs,
                         float* __restrict__ out)
{
    int r = blockIdx.x * blockDim.x + threadIdx.x;
    if (r >= R_RAYS) return;
    float s0 = 0.f, s1 = 0.f, s2 = 0.f;
    for (int s = 0; s < 128; s++) {
        int m = r*128 + s;
        float w = W[m];
        s0 = fmaf(w, rgbs[(size_t)m*3+0], s0);
        s1 = fmaf(w, rgbs[(size_t)m*3+1], s1);
        s2 = fmaf(w, rgbs[(size_t)m*3+2], s2);
    }
    out[r*3+0] = s0; out[r*3+1] = s1; out[r*3+2] = s2;
}

// ===================== host orchestration =====================

enum { EPI_LIN = 0, EPI_SP = 1, EPI_RELU = 2, EPI_MASK = 3 };

static const int GEMM_SHM = 110592;

static void launch_gemm(int epi, int trb, const float* A,
                        const float* Bhi, const float* Blo,
                        const float* bias, const float* Hm, float* C,
                        int M, int N, int K)
{
    dim3 g((N + 127) / 128, (M + 127) / 128);
    if (trb == 0) {
        if (epi == EPI_SP) {
            cudaFuncSetAttribute(gemm_tc<1,0>, cudaFuncAttributeMaxDynamicSharedMemorySize, GEMM_SHM);
            gemm_tc<1,0><<<g,256,GEMM_SHM>>>(A,Bhi,Blo,bias,Hm,C,M,N,K);
        } else if (epi == EPI_RELU) {
            cudaFuncSetAttribute(gemm_tc<2,0>, cudaFuncAttributeMaxDynamicSharedMemorySize, GEMM_SHM);
            gemm_tc<2,0><<<g,256,GEMM_SHM>>>(A,Bhi,Blo,bias,Hm,C,M,N,K);
        } else {
            cudaFuncSetAttribute(gemm_tc<0,0>, cudaFuncAttributeMaxDynamicSharedMemorySize, GEMM_SHM);
            gemm_tc<0,0><<<g,256,GEMM_SHM>>>(A,Bhi,Blo,bias,Hm,C,M,N,K);
        }
    } else {
        if (epi == EPI_MASK) {
            cudaFuncSetAttribute(gemm_tc<3,1>, cudaFuncAttributeMaxDynamicSharedMemorySize, GEMM_SHM);
            gemm_tc<3,1><<<g,256,GEMM_SHM>>>(A,Bhi,Blo,bias,Hm,C,M,N,K);
        } else {
            cudaFuncSetAttribute(gemm_tc<0,1>, cudaFuncAttributeMaxDynamicSharedMemorySize, GEMM_SHM);
            gemm_tc<0,1><<<g,256,GEMM_SHM>>>(A,Bhi,Blo,bias,Hm,C,M,N,K);
        }
    }
}

// pre-split weight accessors (index: sw0..sw8 = 0..8, cw0..cw2 = 9..11)
struct WSplit { const float* hi[12]; const float* lo[12]; };

static void sdf_forward_nostore(int M, const WSplit& W, const float* const* sb,
                                const float* const* sw,
                                float* base, float* sdf_dest)
{
    float* PE  = base + O_E;
    float* PB0 = base + O_B0;
    float* PB1 = base + O_B1;
    float* PP  = base + O_PTS;
    k_embed<<<(M+255)/256, 256>>>(PP, PE, M);
    launch_gemm(EPI_SP, 0, PE,  W.hi[0], W.lo[0], sb[0], nullptr, PB1, M, 256, 39);
    launch_gemm(EPI_SP, 0, PB1, W.hi[1], W.lo[1], sb[1], nullptr, PB0, M, 256, 256);
    launch_gemm(EPI_SP, 0, PB0, W.hi[2], W.lo[2], sb[2], nullptr, PB1, M, 256, 256);
    launch_gemm(EPI_SP, 0, PB1, W.hi[3], W.lo[3], sb[3], nullptr, PB0, M, 217, 256);
    k_concat<<<(M*256+255)/256, 256>>>(PB0, PE, PB1, M);
    launch_gemm(EPI_SP, 0, PB1, W.hi[4], W.lo[4], sb[4], nullptr, PB0, M, 256, 256);
    launch_gemm(EPI_SP, 0, PB0, W.hi[5], W.lo[5], sb[5], nullptr, PB1, M, 256, 256);
    launch_gemm(EPI_SP, 0, PB1, W.hi[6], W.lo[6], sb[6], nullptr, PB0, M, 256, 256);
    launch_gemm(EPI_SP, 0, PB0, W.hi[7], W.lo[7], sb[7], nullptr, PB1, M, 256, 256);
    k_sdf_head<<<(M*32+255)/256, 256>>>(PB1, sw[8], sb[8], sdf_dest, M);
}

extern "C" void kernel_launch(void* const* d_in, const int* in_sizes, int n_in,
                              void* d_out, int out_size)
{
    const float* ro = (const float*)d_in[0];
    const float* rd = (const float*)d_in[1];
    const float* sw[9]; const float* sb[9];
    const float* cw[3]; const float* cb[3];
    const float* var;

    bool interleaved = (in_sizes[3] < 1024);
    if (interleaved) {
        for (int l = 0; l < 9; l++) {
            sw[l] = (const float*)d_in[2 + 2*l];
            sb[l] = (const float*)d_in[3 + 2*l];
        }
        for (int l = 0; l < 3; l++) {
            cw[l] = (const float*)d_in[20 + 2*l];
            cb[l] = (const float*)d_in[21 + 2*l];
        }
        var = (const float*)d_in[26];
    } else {
        for (int l = 0; l < 9; l++) {
            sw[l] = (const float*)d_in[2 + l];
            sb[l] = (const float*)d_in[11 + l];
        }
        for (int l = 0; l < 3; l++) {
            cw[l] = (const float*)d_in[20 + l];
            cb[l] = (const float*)d_in[23 + l];
        }
        var = (const float*)d_in[26];
    }
    float* out = (float*)d_out;

    float* base = nullptr;
    cudaGetSymbolAddress((void**)&base, d_SCRATCH);

    float* PZ = base+O_Z;     float* PSDF = base+O_SDF;
    float* PZT = base+O_ZT;   float* PSDFT = base+O_SDFT;
    float* PZN = base+O_ZNEW; float* PSDFN = base+O_SDFNEW;
    float* PP = base+O_PTS;   float* PD = base+O_DIST;   float* PE = base+O_E;
    float* PH0 = base+O_H0; float* PH1 = base+O_H1; float* PH2 = base+O_H2;
    float* PH3 = base+O_H3; float* PH4 = base+O_H4; float* PH5 = base+O_H5;
    float* PH6 = base+O_H6; float* PH7 = base+O_H7;
    float* PO8 = base+O_OUT8;
    float* PB0 = base+O_B0; float* PB1 = base+O_B1;
    float* PGE = base+O_GE; float* PGR = base+O_GRAD;
    float* PA = base+O_ALPHA; float* PW = base+O_WT; float* PRGB = base+O_RGBS;

    // ---- pre-split all 12 weight matrices into (hi, lo) pools ----
    const float* wsrc[12] = { sw[0], sw[1], sw[2], sw[3], sw[4], sw[5],
                              sw[6], sw[7], sw[8], cw[0], cw[1], cw[2] };
    WSplit W;
    {
        float* whiBase = base + O_WHI;
        float* wloBase = base + O_WLO;
        size_t off = 0;
        for (int i = 0; i < 12; i++) {
            int n = (int)WSZ[i];
            k_wsplit<<<(n+255)/256, 256>>>(wsrc[i], whiBase + off, wloBase + off, n);
            W.hi[i] = whiBase + off;
            W.lo[i] = wloBase + off;
            off += WSZ[i];
        }
    }

    // ---- initial 64 samples + sdf ----
    k_ray_init<<<4, 256>>>(ro, rd, PZ);
    int S = 64;
    int M = R_RAYS * S;
    k_pts<<<(M+255)/256, 256>>>(PZ, ro, rd, PP, S, M);
    sdf_forward_nostore(M, W, sb, sw, base, PSDF);

    // ---- 4 importance-sampling rounds ----
    for (int i = 0; i < 4; i++) {
        float inv_s = 64.0f * (float)(1 << i);
        k_upsample<<<4, 256>>>(ro, rd, PZ, PSDF, PZN, S, inv_s);
        int Mn = R_RAYS * 16;
        k_pts<<<(Mn+255)/256, 256>>>(PZN, ro, rd, PP, 16, Mn);
        sdf_forward_nostore(Mn, W, sb, sw, base, PSDFN);
        k_merge<<<4, 256>>>(PZ, PSDF, PZN, PSDFN, PZT, PSDFT, S);
        S += 16;
        int n = R_RAYS * S;
        k_copy<<<(n+255)/256, 256>>>(PZ, PZT, n);
        k_copy<<<(n+255)/256, 256>>>(PSDF, PSDFT, n);
    }

    // ---- final forward (stored activations) ----
    M = (int)NPTS;
    k_dist_mid_pts<<<(M+255)/256, 256>>>(PZ, ro, rd, PP, PD);
    k_embed<<<(M+255)/256, 256>>>(PP, PE, M);
    launch_gemm(EPI_SP, 0, PE,  W.hi[0], W.lo[0], sb[0], nullptr, PH0, M, 256, 39);
    launch_gemm(EPI_SP, 0, PH0, W.hi[1], W.lo[1], sb[1], nullptr, PH1, M, 256, 256);
    launch_gemm(EPI_SP, 0, PH1, W.hi[2], W.lo[2], sb[2], nullptr, PH2, M, 256, 256);
    launch_gemm(EPI_SP, 0, PH2, W.hi[3], W.lo[3], sb[3], nullptr, PH3, M, 217, 256);
    k_concat<<<(M*256+255)/256, 256>>>(PH3, PE, PH4, M);
    launch_gemm(EPI_SP, 0, PH4, W.hi[4], W.lo[4], sb[4], nullptr, PH5, M, 256, 256);
    launch_gemm(EPI_SP, 0, PH5, W.hi[5], W.lo[5], sb[5], nullptr, PH6, M, 256, 256);
    launch_gemm(EPI_SP, 0, PH6, W.hi[6], W.lo[6], sb[6], nullptr, PH7, M, 256, 256);
    launch_gemm(EPI_SP, 0, PH7, W.hi[7], W.lo[7], sb[7], nullptr, PB0, M, 256, 256);
    launch_gemm(EPI_LIN, 0, PB0, W.hi[8], W.lo[8], sb[8], nullptr, PO8, M, 257, 256);

    // ---- backward (VJP of sdf channel w.r.t. points) ----
    k_bwinit<<<(M*256+255)/256, 256>>>(PB0, sw[8], PB1, M);
    launch_gemm(EPI_MASK, 1, PB1, W.hi[7], W.lo[7], nullptr, PH7, PB0, M, 256, 256);
    launch_gemm(EPI_MASK, 1, PB0, W.hi[6], W.lo[6], nullptr, PH6, PB1, M, 256, 256);
    launch_gemm(EPI_MASK, 1, PB1, W.hi[5], W.lo[5], nullptr, PH5, PB0, M, 256, 256);
    launch_gemm(EPI_LIN,  1, PB0, W.hi[4], W.lo[4], nullptr, nullptr, PB1, M, 256, 256);
    k_split<<<(M*256+255)/256, 256>>>(PB1, PH3, PB0, PGE, M);
    launch_gemm(EPI_MASK, 1, PB0, W.hi[3], W.lo[3], nullptr, PH2, PB1, M, 256, 217);
    launch_gemm(EPI_MASK, 1, PB1, W.hi[2], W.lo[2], nullptr, PH1, PB0, M, 256, 256);
    launch_gemm(EPI_MASK, 1, PB0, W.hi[1], W.lo[1], nullptr, PH0, PB1, M, 256, 256);
    launch_gemm(EPI_LIN,  1, PB1, W.hi[0], W.lo[0], nullptr, nullptr, PB0, M, 39, 256);
    k_gradpts<<<(M+255)/256, 256>>>(PB0, PGE, PP, PGR, M);

    // ---- color net + compositing ----
    k_alpha<<<(M+255)/256, 256>>>(PO8, PGR, PD, rd, var, PA, M);
    k_ray_weights<<<4, 256>>>(PA, PW);
    k_cin<<<(M*265+255)/256, 256>>>(PP, rd, PGR, PO8, PB0, M);
    launch_gemm(EPI_RELU, 0, PB0, W.hi[9],  W.lo[9],  cb[0], nullptr, PB1, M, 256, 265);
    launch_gemm(EPI_RELU, 0, PB1, W.hi[10], W.lo[10], cb[1], nullptr, PB0, M, 256, 256);
    k_color_head<<<(M*32+255)/256, 256>>>(PB0, cw[2], cb[2], PRGB, M);
    k_reduce<<<4, 256>>>(PW, PRGB, out);
}

// round 9
// speedup vs baseline: 1.3922x; 1.3922x over previous
#include <cuda_runtime.h>
#include <math.h>
#include <stdint.h>
#include <stddef.h>

#define R_RAYS 1024
static constexpr size_t NPTS = 131072;

constexpr size_t O_Z      = 0;
constexpr size_t O_SDF    = O_Z + NPTS;
constexpr size_t O_ZT     = O_SDF + NPTS;
constexpr size_t O_SDFT   = O_ZT + NPTS;
constexpr size_t O_ZNEW   = O_SDFT + NPTS;
constexpr size_t O_SDFNEW = O_ZNEW + 1024 * 16;
constexpr size_t O_PTS    = O_SDFNEW + 1024 * 16;
constexpr size_t O_DIST   = O_PTS + NPTS * 3;
constexpr size_t O_E      = O_DIST + NPTS;
constexpr size_t O_H0     = O_E + NPTS * 39;
constexpr size_t O_H1     = O_H0 + NPTS * 256;
constexpr size_t O_H2     = O_H1 + NPTS * 256;
constexpr size_t O_H3     = O_H2 + NPTS * 256;
constexpr size_t O_H4     = O_H3 + NPTS * 217;
constexpr size_t O_H5     = O_H4 + NPTS * 256;
constexpr size_t O_H6     = O_H5 + NPTS * 256;
constexpr size_t O_H7     = O_H6 + NPTS * 256;
constexpr size_t O_OUT8   = O_H7 + NPTS * 256;
constexpr size_t O_B0     = O_OUT8 + NPTS * 257;
constexpr size_t O_B1     = O_B0 + NPTS * 265;
constexpr size_t O_GE     = O_B1 + NPTS * 265;
constexpr size_t O_GRAD   = O_GE + NPTS * 39;
constexpr size_t O_ALPHA  = O_GRAD + NPTS * 3;
constexpr size_t O_WT     = O_ALPHA + NPTS;
constexpr size_t O_RGBS   = O_WT + NPTS;
constexpr size_t SCRATCH_TOTAL = O_RGBS + NPTS * 3;

__device__ __align__(256) float d_SCRATCH[SCRATCH_TOTAL];

__device__ __forceinline__ float sigmoidf_(float x) { return 1.0f / (1.0f + expf(-x)); }

// truncation-based tf32x3 split: HW reads only the top 19 bits of a tf32
// operand (low 13 mantissa bits ignored), so hi = bits&0xFFFFE000 matches the
// value the MMA actually uses, and lo = v - hi is the exact residual.
__device__ __forceinline__ void split2(float v, uint32_t& H, uint32_t& L) {
    uint32_t hu = __float_as_uint(v) & 0xffffe000u;
    H = hu;
    L = __float_as_uint(v - __uint_as_float(hu));
}

__device__ __forceinline__ uint32_t s2u(const void* p) {
    return (uint32_t)__cvta_generic_to_shared(p);
}
__device__ __forceinline__ void cpa16(uint32_t d, const void* s, int sz) {
    asm volatile("cp.async.ca.shared.global [%0], [%1], 16, %2;" :: "r"(d), "l"(s), "r"(sz));
}
__device__ __forceinline__ void cpa4(uint32_t d, const void* s, int sz) {
    asm volatile("cp.async.ca.shared.global [%0], [%1], 4, %2;" :: "r"(d), "l"(s), "r"(sz));
}
#define CP_COMMIT() asm volatile("cp.async.commit_group;")
#define CP_WAIT1()  asm volatile("cp.async.wait_group 1;")

// ============================================================================
// TF32x3 tensor-core GEMM, 2-stage cp.async pipeline, kTile=32.
// C[M,N] = epi(A[M,K] @ B + bias); fp32-accurate via truncation hi/lo split
// at fragment-load time. acc += aH*bL + aL*bH + aH*bH.
// TRB=0: B is [K,N] row-major.  TRB=1: B is [N,K] row-major (C = A @ B^T)
// EPI: 0 linear, 1 softplus(100x)/100, 2 relu, 3 multiply by -expm1(-100*Hm)
// CTA tile 128x128; 8 warps (4 M x 2 N), warp tile 32x64. 2 CTAs/SM pinned.
// ============================================================================
template <int EPI, int TRB>
__global__ void __launch_bounds__(256, 2) gemm_tc(
    const float* __restrict__ A, const float* __restrict__ B,
    const float* __restrict__ bias, const float* __restrict__ Hm,
    float* __restrict__ C, int M, int N, int K)
{
    extern __shared__ float sm[];
    constexpr int AP = 36;
    constexpr int BP = TRB ? 36 : 136;
    constexpr int A_TILE = 128 * AP;
    constexpr int B_TILE = TRB ? (128 * 36) : (32 * 136);
    float* As0 = sm;
    float* As1 = sm + A_TILE;
    float* Bs0 = sm + 2 * A_TILE;
    float* Bs1 = sm + 2 * A_TILE + B_TILE;

    const int tid  = threadIdx.x;
    const int wid  = tid >> 5;
    const int lane = tid & 31;
    const int wm = wid & 3;
    const int wn = wid >> 2;
    const int m0 = blockIdx.y * 128;
    const int n0 = blockIdx.x * 128;
    const int r  = lane >> 2;
    const int cq = lane & 3;
    const bool alA = (K & 3) == 0;
    const bool alB = TRB ? alA : ((N & 3) == 0);

    float acc[2][8][4] = {};

    const int nsteps = (K + 31) >> 5;

    auto load_stage = [&](float* Asx, float* Bsx, int k0) {
        // ---- A: 128 rows x 32 k; thread -> row=tid>>1, 16-float half
        {
            int row = tid >> 1;
            int c0  = (tid & 1) * 16;
            int gm  = m0 + row;
            const float* src = A + ((gm < M) ? ((size_t)gm * K + k0 + c0) : 0);
            float* dst = Asx + row * AP + c0;
            if (alA) {
#pragma unroll
                for (int c = 0; c < 16; c += 4) {
                    int rem = (gm < M) ? (K - (k0 + c0 + c)) : 0;
                    rem = rem > 4 ? 4 : (rem < 0 ? 0 : rem);
                    cpa16(s2u(dst + c), src + c, rem * 4);
                }
            } else {
#pragma unroll
                for (int c = 0; c < 16; c++) {
                    int ok = (gm < M && (k0 + c0 + c) < K) ? 4 : 0;
                    cpa4(s2u(dst + c), src + c, ok);
                }
            }
        }
        // ---- B tile -> Bs[k][n] (TRB=0) or Bs[n][k] (TRB=1)
        if (TRB == 0) {
            int kk = tid >> 3;
            int c0 = (tid & 7) * 16;
            int gk = k0 + kk;
            const float* src = B + ((gk < K) ? ((size_t)gk * N + n0 + c0) : 0);
            float* dst = Bsx + kk * BP + c0;
            if (alB) {
#pragma unroll
                for (int c = 0; c < 16; c += 4) {
                    int rem = (gk < K) ? (N - (n0 + c0 + c)) : 0;
                    rem = rem > 4 ? 4 : (rem < 0 ? 0 : rem);
                    cpa16(s2u(dst + c), src + c, rem * 4);
                }
            } else {
#pragma unroll
                for (int c = 0; c < 16; c++) {
                    int ok = (gk < K && (n0 + c0 + c) < N) ? 4 : 0;
                    cpa4(s2u(dst + c), src + c, ok);
                }
            }
        } else {
            int nn = tid >> 1;
            int c0 = (tid & 1) * 16;
            int gn = n0 + nn;
            const float* src = B + ((gn < N) ? ((size_t)gn * K + k0 + c0) : 0);
            float* dst = Bsx + nn * BP + c0;
            if (alB) {
#pragma unroll
                for (int c = 0; c < 16; c += 4) {
                    int rem = (gn < N) ? (K - (k0 + c0 + c)) : 0;
                    rem = rem > 4 ? 4 : (rem < 0 ? 0 : rem);
                    cpa16(s2u(dst + c), src + c, rem * 4);
                }
            } else {
#pragma unroll
                for (int c = 0; c < 16; c++) {
                    int ok = (gn < N && (k0 + c0 + c) < K) ? 4 : 0;
                    cpa4(s2u(dst + c), src + c, ok);
                }
            }
        }
    };

    load_stage(As0, Bs0, 0);
    CP_COMMIT();

    for (int s = 0; s < nsteps; s++) {
        if (s + 1 < nsteps)
            load_stage(((s + 1) & 1) ? As1 : As0, ((s + 1) & 1) ? Bs1 : Bs0, (s + 1) * 32);
        CP_COMMIT();
        CP_WAIT1();
        __syncthreads();

        const float* Ast = (s & 1) ? As1 : As0;
        const float* Bst = (s & 1) ? Bs1 : Bs0;

#pragma unroll
        for (int k8 = 0; k8 < 32; k8 += 8) {
            uint32_t aH[2][4], aL[2][4];
#pragma unroll
            for (int i = 0; i < 2; i++) {
                int rb = wm * 32 + i * 16 + r;
                split2(Ast[rb * AP + k8 + cq],           aH[i][0], aL[i][0]);
                split2(Ast[(rb + 8) * AP + k8 + cq],     aH[i][1], aL[i][1]);
                split2(Ast[rb * AP + k8 + cq + 4],       aH[i][2], aL[i][2]);
                split2(Ast[(rb + 8) * AP + k8 + cq + 4], aH[i][3], aL[i][3]);
            }
#pragma unroll
            for (int j = 0; j < 8; j++) {
                int cb = wn * 64 + j * 8 + r;
                float b0raw = TRB ? Bst[cb * BP + k8 + cq]     : Bst[(k8 + cq) * BP + cb];
                float b1raw = TRB ? Bst[cb * BP + k8 + cq + 4] : Bst[(k8 + cq + 4) * BP + cb];
                uint32_t bH0, bL0, bH1, bL1;
                split2(b0raw, bH0, bL0);
                split2(b1raw, bH1, bL1);
#pragma unroll
                for (int i = 0; i < 2; i++) {
                    asm volatile(
                        "mma.sync.aligned.m16n8k8.row.col.f32.tf32.tf32.f32 "
                        "{%0,%1,%2,%3}, {%4,%5,%6,%7}, {%8,%9}, {%0,%1,%2,%3};"
                        : "+f"(acc[i][j][0]), "+f"(acc[i][j][1]),
                          "+f"(acc[i][j][2]), "+f"(acc[i][j][3])
                        : "r"(aH[i][0]), "r"(aH[i][1]), "r"(aH[i][2]), "r"(aH[i][3]),
                          "r"(bL0), "r"(bL1));
                    asm volatile(
                        "mma.sync.aligned.m16n8k8.row.col.f32.tf32.tf32.f32 "
                        "{%0,%1,%2,%3}, {%4,%5,%6,%7}, {%8,%9}, {%0,%1,%2,%3};"
                        : "+f"(acc[i][j][0]), "+f"(acc[i][j][1]),
                          "+f"(acc[i][j][2]), "+f"(acc[i][j][3])
                        : "r"(aL[i][0]), "r"(aL[i][1]), "r"(aL[i][2]), "r"(aL[i][3]),
                          "r"(bH0), "r"(bH1));
                    asm volatile(
                        "mma.sync.aligned.m16n8k8.row.col.f32.tf32.tf32.f32 "
                        "{%0,%1,%2,%3}, {%4,%5,%6,%7}, {%8,%9}, {%0,%1,%2,%3};"
                        : "+f"(acc[i][j][0]), "+f"(acc[i][j][1]),
                          "+f"(acc[i][j][2]), "+f"(acc[i][j][3])
                        : "r"(aH[i][0]), "r"(aH[i][1]), "r"(aH[i][2]), "r"(aH[i][3]),
                          "r"(bH0), "r"(bH1));
                }
            }
        }
        __syncthreads();
    }

    // ---- epilogue
#pragma unroll
    for (int i = 0; i < 2; i++) {
        int row0 = m0 + wm * 32 + i * 16 + r;
#pragma unroll
        for (int j = 0; j < 8; j++) {
            int col0 = n0 + wn * 64 + j * 8 + cq * 2;
#pragma unroll
            for (int t = 0; t < 4; t++) {
                int row = row0 + (t >> 1) * 8;
                int col = col0 + (t & 1);
                if (row < M && col < N) {
                    float v = acc[i][j][t];
                    if (bias) v += bias[col];
                    if (EPI == 1) {
                        float s = 100.0f * v;
                        v = (fmaxf(s, 0.0f) + log1pf(expf(-fabsf(s)))) * 0.01f;
                    } else if (EPI == 2) {
                        v = fmaxf(v, 0.0f);
                    } else if (EPI == 3) {
                        v = v * (-expm1f(-100.0f * Hm[(size_t)row * N + col]));
                    }
                    C[(size_t)row * N + col] = v;
                }
            }
        }
    }
}

// ===================== small kernels =====================

__global__ void k_ray_init(const float* __restrict__ ro, const float* __restrict__ rd,
                           float* __restrict__ Z)
{
    int r = blockIdx.x * blockDim.x + threadIdx.x;
    if (r >= R_RAYS) return;
    float ox = ro[r*3], oy = ro[r*3+1], oz = ro[r*3+2];
    float dx = rd[r*3], dy = rd[r*3+1], dz = rd[r*3+2];
    float a = dx*dx + dy*dy + dz*dz;
    float b = 2.0f * (ox*dx + oy*dy + oz*dz);
    float mid = -b / (2.0f * a);
    float nv = fmaxf(mid - 1.0f, 0.05f);
    float fv = mid + 1.0f;
    for (int s = 0; s < 64; s++)
        Z[r*64 + s] = nv + (fv - nv) * ((float)s * (1.0f/63.0f));
}

__global__ void k_pts(const float* __restrict__ Z, const float* __restrict__ ro,
                      const float* __restrict__ rd, float* __restrict__ P, int S, int M)
{
    int m = blockIdx.x * blockDim.x + threadIdx.x;
    if (m >= M) return;
    int r = m / S;
    float z = Z[m];
#pragma unroll
    for (int j = 0; j < 3; j++)
        P[(size_t)m*3 + j] = fmaf(rd[r*3+j], z, ro[r*3+j]);
}

__global__ void k_dist_mid_pts(const float* __restrict__ Z, const float* __restrict__ ro,
                               const float* __restrict__ rd, float* __restrict__ P,
                               float* __restrict__ D)
{
    int m = blockIdx.x * blockDim.x + threadIdx.x;
    if (m >= (int)NPTS) return;
    int s = m & 127, r = m >> 7;
    float z = Z[m];
    float d = (s < 127) ? (Z[m+1] - z) : 0.03125f;
    D[m] = d;
    float mz = fmaf(0.5f, d, z);
#pragma unroll
    for (int j = 0; j < 3; j++)
        P[(size_t)m*3 + j] = fmaf(rd[r*3+j], mz, ro[r*3+j]);
}

__global__ void k_embed(const float* __restrict__ P, float* __restrict__ E, int M)
{
    int m = blockIdx.x * blockDim.x + threadIdx.x;
    if (m >= M) return;
    float p0 = P[(size_t)m*3], p1 = P[(size_t)m*3+1], p2 = P[(size_t)m*3+2];
    float* e = E + (size_t)m*39;
    e[0] = p0; e[1] = p1; e[2] = p2;
    float f = 1.0f;
#pragma unroll
    for (int k = 0; k < 6; k++) {
        float s0,c0,s1,c1,s2,c2;
        sincosf(f*p0,&s0,&c0); sincosf(f*p1,&s1,&c1); sincosf(f*p2,&s2,&c2);
        e[3+6*k+0]=s0; e[3+6*k+1]=s1; e[3+6*k+2]=s2;
        e[3+6*k+3]=c0; e[3+6*k+4]=c1; e[3+6*k+5]=c2;
        f *= 2.0f;
    }
}

__global__ void k_concat(const float* __restrict__ H3, const float* __restrict__ E,
                         float* __restrict__ O, int M)
{
    int idx = blockIdx.x * blockDim.x + threadIdx.x;
    if (idx >= M * 256) return;
    int m = idx >> 8, c = idx & 255;
    float v = (c < 217) ? H3[(size_t)m*217 + c] : E[(size_t)m*39 + (c-217)];
    O[idx] = v * 0.7071067811865476f;
}

__global__ void k_sdf_head(const float* __restrict__ H, const float* __restrict__ W8,
                           const float* __restrict__ b8, float* __restrict__ out, int M)
{
    int gw = (blockIdx.x * blockDim.x + threadIdx.x) >> 5;
    int lane = threadIdx.x & 31;
    if (gw >= M) return;
    const float* h = H + (size_t)gw * 256;
    float s = 0.0f;
#pragma unroll
    for (int k = lane; k < 256; k += 32) s = fmaf(h[k], W8[(size_t)k*257], s);
#pragma unroll
    for (int o = 16; o; o >>= 1) s += __shfl_xor_sync(0xffffffffu, s, o);
    if (!lane) out[gw] = s + b8[0];
}

__global__ void k_upsample(const float* __restrict__ ro, const float* __restrict__ rd,
                           const float* __restrict__ Z, const float* __restrict__ SD,
                           float* __restrict__ ZN, int S, float inv_s)
{
    int r = blockIdx.x * blockDim.x + threadIdx.x;
    if (r >= R_RAYS) return;
    float ox = ro[r*3], oy = ro[r*3+1], oz = ro[r*3+2];
    float dx = rd[r*3], dy = rd[r*3+1], dz = rd[r*3+2];
    const float* zr = Z + (size_t)r * S;
    const float* sr = SD + (size_t)r * S;

    float w[128], cdf[129];
    float prev_raw = 0.0f, T = 1.0f, wsum = 0.0f;
    float z_i = zr[0];
    float px = fmaf(dx,z_i,ox), py = fmaf(dy,z_i,oy), pz = fmaf(dz,z_i,oz);
    float rad_i = sqrtf(px*px + py*py + pz*pz);
    float sdf_i = sr[0];

    for (int i = 0; i < S - 1; i++) {
        float z_n = zr[i+1], sdf_n = sr[i+1];
        float qx = fmaf(dx,z_n,ox), qy = fmaf(dy,z_n,oy), qz = fmaf(dz,z_n,oz);
        float rad_n = sqrtf(qx*qx + qy*qy + qz*qz);
        bool inside = (rad_i < 1.0f) || (rad_n < 1.0f);
        float mid_sdf = 0.5f * (sdf_i + sdf_n);
        float raw = (sdf_n - sdf_i) / (z_n - z_i + 1e-5f);
        float cosv = fminf(raw, prev_raw);
        prev_raw = raw;
        cosv = fminf(fmaxf(cosv, -1000.0f), 0.0f);
        if (!inside) cosv = 0.0f;
        float dist = z_n - z_i;
        float pc = sigmoidf_((mid_sdf - cosv*dist*0.5f) * inv_s);
        float nc = sigmoidf_((mid_sdf + cosv*dist*0.5f) * inv_s);
        float alpha = (pc - nc + 1e-5f) / (pc + 1e-5f);
        float wi = alpha * T;
        T *= (1.0f - alpha + 1e-7f);
        wi += 1e-5f;
        w[i] = wi; wsum += wi;
        z_i = z_n; rad_i = rad_n; sdf_i = sdf_n;
    }

    cdf[0] = 0.0f;
    float invsum = 1.0f / wsum;
    for (int i = 0; i < S - 1; i++) cdf[i+1] = cdf[i] + w[i] * invsum;

    for (int j = 0; j < 16; j++) {
        float u = 0.03125f + (float)j * 0.0625f;
        int lo = 0, hi = S;
        while (lo < hi) { int md = (lo + hi) >> 1; if (cdf[md] <= u) lo = md + 1; else hi = md; }
        int below = lo - 1; if (below < 0) below = 0; if (below > S-1) below = S-1;
        int above = lo;     if (above > S-1) above = S-1;
        float c0 = cdf[below], c1 = cdf[above];
        float b0 = zr[below],  b1 = zr[above];
        float den = (c1 - c0) < 1e-5f ? 1.0f : (c1 - c0);
        ZN[r*16 + j] = b0 + (u - c0) / den * (b1 - b0);
    }
}

__global__ void k_merge(const float* __restrict__ Z, const float* __restrict__ SD,
                        const float* __restrict__ ZN, const float* __restrict__ SN,
                        float* __restrict__ ZT, float* __restrict__ ST, int S)
{
    int r = blockIdx.x * blockDim.x + threadIdx.x;
    if (r >= R_RAYS) return;
    const float* zo = Z + (size_t)r*S;  const float* so = SD + (size_t)r*S;
    const float* zn = ZN + r*16;        const float* sn = SN + r*16;
    float* zt = ZT + (size_t)r*(S+16);  float* st = ST + (size_t)r*(S+16);
    int i = 0, j = 0;
    for (int k = 0; k < S + 16; k++) {
        bool useOld = (i < S) && ((j >= 16) || (zo[i] <= zn[j]));
        if (useOld) { zt[k] = zo[i]; st[k] = so[i]; i++; }
        else        { zt[k] = zn[j]; st[k] = sn[j]; j++; }
    }
}

__global__ void k_copy(float* __restrict__ dst, const float* __restrict__ src, int n)
{
    int i = blockIdx.x * blockDim.x + threadIdx.x;
    if (i < n) dst[i] = src[i];
}

__global__ void k_bwinit(const float* __restrict__ H7, const float* __restrict__ W8,
                         float* __restrict__ G, int M)
{
    int idx = blockIdx.x * blockDim.x + threadIdx.x;
    if (idx >= M * 256) return;
    int c = idx & 255;
    G[idx] = W8[(size_t)c * 257] * (-expm1f(-100.0f * H7[idx]));
}

__global__ void k_split(const float* __restrict__ Gin4, const float* __restrict__ H3,
                        float* __restrict__ Gz3, float* __restrict__ GE, int M)
{
    int idx = blockIdx.x * blockDim.x + threadIdx.x;
    if (idx >= M * 256) return;
    int m = idx >> 8, c = idx & 255;
    float v = Gin4[idx] * 0.7071067811865476f;
    if (c < 217)
        Gz3[(size_t)m*217 + c] = v * (-expm1f(-100.0f * H3[(size_t)m*217 + c]));
    else
        GE[(size_t)m*39 + (c - 217)] = v;
}

__global__ void k_gradpts(const float* __restrict__ GEm, const float* __restrict__ GEs,
                          const float* __restrict__ P, float* __restrict__ GR, int M)
{
    int m = blockIdx.x * blockDim.x + threadIdx.x;
    if (m >= M) return;
    const float* ga = GEm + (size_t)m*39;
    const float* gb = GEs + (size_t)m*39;
    float p[3] = {P[(size_t)m*3], P[(size_t)m*3+1], P[(size_t)m*3+2]};
    float g[3];
#pragma unroll
    for (int j = 0; j < 3; j++) g[j] = ga[j] + gb[j];
    float f = 1.0f;
#pragma unroll
    for (int k = 0; k < 6; k++) {
#pragma unroll
        for (int j = 0; j < 3; j++) {
            float s, c;
            sincosf(f * p[j], &s, &c);
            float gs = ga[3+6*k+j]   + gb[3+6*k+j];
            float gc = ga[3+6*k+3+j] + gb[3+6*k+3+j];
            g[j] = fmaf( f * c, gs, g[j]);
            g[j] = fmaf(-f * s, gc, g[j]);
        }
        f *= 2.0f;
    }
#pragma unroll
    for (int j = 0; j < 3; j++) GR[(size_t)m*3 + j] = g[j];
}

__global__ void k_alpha(const float* __restrict__ OUT8, const float* __restrict__ GR,
                        const float* __restrict__ D, const float* __restrict__ rd,
                        const float* __restrict__ var, float* __restrict__ A, int M)
{
    int m = blockIdx.x * blockDim.x + threadIdx.x;
    if (m >= M) return;
    int r = m >> 7;
    float tc = rd[r*3]*GR[(size_t)m*3] + rd[r*3+1]*GR[(size_t)m*3+1] + rd[r*3+2]*GR[(size_t)m*3+2];
    float ic = fminf(tc, 0.0f);
    float sdf = OUT8[(size_t)m * 257];
    float dist = D[m];
    float inv_s = fminf(fmaxf(expf(10.0f * var[0]), 1e-6f), 1e6f);
    float pc = sigmoidf_((sdf - ic*dist*0.5f) * inv_s);
    float nc = sigmoidf_((sdf + ic*dist*0.5f) * inv_s);
    float a = (pc - nc + 1e-5f) / (pc + 1e-5f);
    A[m] = fminf(fmaxf(a, 0.0f), 1.0f);
}

__global__ void k_ray_weights(const float* __restrict__ A, float* __restrict__ W)
{
    int r = blockIdx.x * blockDim.x + threadIdx.x;
    if (r >= R_RAYS) return;
    float T = 1.0f;
    for (int s = 0; s < 128; s++) {
        int m = r*128 + s;
        float a = A[m];
        W[m] = a * T;
        T *= (1.0f - a + 1e-7f);
    }
}

__global__ void k_cin(const float* __restrict__ P, const float* __restrict__ rd,
                      const float* __restrict__ GR, const float* __restrict__ OUT8,
                      float* __restrict__ CIN, int M)
{
    int idx = blockIdx.x * blockDim.x + threadIdx.x;
    if (idx >= M * 265) return;
    int m = idx / 265, c = idx % 265;
    float v;
    if (c < 3) v = P[(size_t)m*3 + c];
    else if (c < 6) { int r = m >> 7; v = rd[r*3 + (c-3)]; }
    else if (c < 9) {
        float g0 = GR[(size_t)m*3], g1 = GR[(size_t)m*3+1], g2 = GR[(size_t)m*3+2];
        float n = fmaxf(sqrtf(g0*g0 + g1*g1 + g2*g2), 1e-6f);
        v = GR[(size_t)m*3 + (c-6)] / n;
    } else v = OUT8[(size_t)m*257 + 1 + (c-9)];
    CIN[idx] = v;
}

__global__ void k_color_head(const float* __restrict__ H, const float* __restrict__ W,
                             const float* __restrict__ b, float* __restrict__ rgbs, int M)
{
    int gw = (blockIdx.x * blockDim.x + threadIdx.x) >> 5;
    int lane = threadIdx.x & 31;
    if (gw >= M) return;
    const float* h = H + (size_t)gw * 256;
    float a0 = 0.f, a1 = 0.f, a2 = 0.f;
#pragma unroll
    for (int k = lane; k < 256; k += 32) {
        float hv = h[k];
        a0 = fmaf(hv, W[k*3+0], a0);
        a1 = fmaf(hv, W[k*3+1], a1);
        a2 = fmaf(hv, W[k*3+2], a2);
    }
#pragma unroll
    for (int o = 16; o; o >>= 1) {
        a0 += __shfl_xor_sync(0xffffffffu, a0, o);
        a1 += __shfl_xor_sync(0xffffffffu, a1, o);
        a2 += __shfl_xor_sync(0xffffffffu, a2, o);
    }
    if (!lane) {
        rgbs[(size_t)gw*3+0] = sigmoidf_(a0 + b[0]);
        rgbs[(size_t)gw*3+1] = sigmoidf_(a1 + b[1]);
        rgbs[(size_t)gw*3+2] = sigmoidf_(a2 + b[2]);
    }
}

__global__ void k_reduce(const float* __restrict__ W, const float* __restrict__ rgbs,
                         float* __restrict__ out)
{
    int r = blockIdx.x * blockDim.x + threadIdx.x;
    if (r >= R_RAYS) return;
    float s0 = 0.f, s1 = 0.f, s2 = 0.f;
    for (int s = 0; s < 128; s++) {
        int m = r*128 + s;
        float w = W[m];
        s0 = fmaf(w, rgbs[(size_t)m*3+0], s0);
        s1 = fmaf(w, rgbs[(size_t)m*3+1], s1);
        s2 = fmaf(w, rgbs[(size_t)m*3+2], s2);
    }
    out[r*3+0] = s0; out[r*3+1] = s1; out[r*3+2] = s2;
}

// ===================== host orchestration =====================

enum { EPI_LIN = 0, EPI_SP = 1, EPI_RELU = 2, EPI_MASK = 3 };

static const int GEMM_SHM = 73728;

static void launch_gemm(int epi, int trb, const float* A, const float* B,
                        const float* bias, const float* Hm, float* C,
                        int M, int N, int K)
{
    dim3 g((N + 127) / 128, (M + 127) / 128);
    if (trb == 0) {
        if (epi == EPI_SP) {
            cudaFuncSetAttribute(gemm_tc<1,0>, cudaFuncAttributeMaxDynamicSharedMemorySize, GEMM_SHM);
            gemm_tc<1,0><<<g,256,GEMM_SHM>>>(A,B,bias,Hm,C,M,N,K);
        } else if (epi == EPI_RELU) {
            cudaFuncSetAttribute(gemm_tc<2,0>, cudaFuncAttributeMaxDynamicSharedMemorySize, GEMM_SHM);
            gemm_tc<2,0><<<g,256,GEMM_SHM>>>(A,B,bias,Hm,C,M,N,K);
        } else {
            cudaFuncSetAttribute(gemm_tc<0,0>, cudaFuncAttributeMaxDynamicSharedMemorySize, GEMM_SHM);
            gemm_tc<0,0><<<g,256,GEMM_SHM>>>(A,B,bias,Hm,C,M,N,K);
        }
    } else {
        if (epi == EPI_MASK) {
            cudaFuncSetAttribute(gemm_tc<3,1>, cudaFuncAttributeMaxDynamicSharedMemorySize, GEMM_SHM);
            gemm_tc<3,1><<<g,256,GEMM_SHM>>>(A,B,bias,Hm,C,M,N,K);
        } else {
            cudaFuncSetAttribute(gemm_tc<0,1>, cudaFuncAttributeMaxDynamicSharedMemorySize, GEMM_SHM);
            gemm_tc<0,1><<<g,256,GEMM_SHM>>>(A,B,bias,Hm,C,M,N,K);
        }
    }
}

static void sdf_forward_nostore(int M, const float* const* sw, const float* const* sb,
                                float* base, float* sdf_dest)
{
    float* PE  = base + O_E;
    float* PB0 = base + O_B0;
    float* PB1 = base + O_B1;
    float* PP  = base + O_PTS;
    k_embed<<<(M+255)/256, 256>>>(PP, PE, M);
    launch_gemm(EPI_SP, 0, PE,  sw[0], sb[0], nullptr, PB1, M, 256, 39);
    launch_gemm(EPI_SP, 0, PB1, sw[1], sb[1], nullptr, PB0, M, 256, 256);
    launch_gemm(EPI_SP, 0, PB0, sw[2], sb[2], nullptr, PB1, M, 256, 256);
    launch_gemm(EPI_SP, 0, PB1, sw[3], sb[3], nullptr, PB0, M, 217, 256);
    k_concat<<<(M*256+255)/256, 256>>>(PB0, PE, PB1, M);
    launch_gemm(EPI_SP, 0, PB1, sw[4], sb[4], nullptr, PB0, M, 256, 256);
    launch_gemm(EPI_SP, 0, PB0, sw[5], sb[5], nullptr, PB1, M, 256, 256);
    launch_gemm(EPI_SP, 0, PB1, sw[6], sb[6], nullptr, PB0, M, 256, 256);
    launch_gemm(EPI_SP, 0, PB0, sw[7], sb[7], nullptr, PB1, M, 256, 256);
    k_sdf_head<<<(M*32+255)/256, 256>>>(PB1, sw[8], sb[8], sdf_dest, M);
}

extern "C" void kernel_launch(void* const* d_in, const int* in_sizes, int n_in,
                              void* d_out, int out_size)
{
    const float* ro = (const float*)d_in[0];
    const float* rd = (const float*)d_in[1];
    const float* sw[9]; const float* sb[9];
    const float* cw[3]; const float* cb[3];
    const float* var;

    bool interleaved = (in_sizes[3] < 1024);
    if (interleaved) {
        for (int l = 0; l < 9; l++) {
            sw[l] = (const float*)d_in[2 + 2*l];
            sb[l] = (const float*)d_in[3 + 2*l];
        }
        for (int l = 0; l < 3; l++) {
            cw[l] = (const float*)d_in[20 + 2*l];
            cb[l] = (const float*)d_in[21 + 2*l];
        }
        var = (const float*)d_in[26];
    } else {
        for (int l = 0; l < 9; l++) {
            sw[l] = (const float*)d_in[2 + l];
            sb[l] = (const float*)d_in[11 + l];
        }
        for (int l = 0; l < 3; l++) {
            cw[l] = (const float*)d_in[20 + l];
            cb[l] = (const float*)d_in[23 + l];
        }
        var = (const float*)d_in[26];
    }
    float* out = (float*)d_out;

    float* base = nullptr;
    cudaGetSymbolAddress((void**)&base, d_SCRATCH);

    float* PZ = base+O_Z;     float* PSDF = base+O_SDF;
    float* PZT = base+O_ZT;   float* PSDFT = base+O_SDFT;
    float* PZN = base+O_ZNEW; float* PSDFN = base+O_SDFNEW;
    float* PP = base+O_PTS;   float* PD = base+O_DIST;   float* PE = base+O_E;
    float* PH0 = base+O_H0; float* PH1 = base+O_H1; float* PH2 = base+O_H2;
    float* PH3 = base+O_H3; float* PH4 = base+O_H4; float* PH5 = base+O_H5;
    float* PH6 = base+O_H6; float* PH7 = base+O_H7;
    float* PO8 = base+O_OUT8;
    float* PB0 = base+O_B0; float* PB1 = base+O_B1;
    float* PGE = base+O_GE; float* PGR = base+O_GRAD;
    float* PA = base+O_ALPHA; float* PW = base+O_WT; float* PRGB = base+O_RGBS;

    // ---- initial 64 samples + sdf ----
    k_ray_init<<<4, 256>>>(ro, rd, PZ);
    int S = 64;
    int M = R_RAYS * S;
    k_pts<<<(M+255)/256, 256>>>(PZ, ro, rd, PP, S, M);
    sdf_forward_nostore(M, sw, sb, base, PSDF);

    // ---- 4 importance-sampling rounds ----
    for (int i = 0; i < 4; i++) {
        float inv_s = 64.0f * (float)(1 << i);
        k_upsample<<<4, 256>>>(ro, rd, PZ, PSDF, PZN, S, inv_s);
        int Mn = R_RAYS * 16;
        k_pts<<<(Mn+255)/256, 256>>>(PZN, ro, rd, PP, 16, Mn);
        sdf_forward_nostore(Mn, sw, sb, base, PSDFN);
        k_merge<<<4, 256>>>(PZ, PSDF, PZN, PSDFN, PZT, PSDFT, S);
        S += 16;
        int n = R_RAYS * S;
        k_copy<<<(n+255)/256, 256>>>(PZ, PZT, n);
        k_copy<<<(n+255)/256, 256>>>(PSDF, PSDFT, n);
    }

    // ---- final forward (stored activations) ----
    M = (int)NPTS;
    k_dist_mid_pts<<<(M+255)/256, 256>>>(PZ, ro, rd, PP, PD);
    k_embed<<<(M+255)/256, 256>>>(PP, PE, M);
    launch_gemm(EPI_SP, 0, PE,  sw[0], sb[0], nullptr, PH0, M, 256, 39);
    launch_gemm(EPI_SP, 0, PH0, sw[1], sb[1], nullptr, PH1, M, 256, 256);
    launch_gemm(EPI_SP, 0, PH1, sw[2], sb[2], nullptr, PH2, M, 256, 256);
    launch_gemm(EPI_SP, 0, PH2, sw[3], sb[3], nullptr, PH3, M, 217, 256);
    k_concat<<<(M*256+255)/256, 256>>>(PH3, PE, PH4, M);
    launch_gemm(EPI_SP, 0, PH4, sw[4], sb[4], nullptr, PH5, M, 256, 256);
    launch_gemm(EPI_SP, 0, PH5, sw[5], sb[5], nullptr, PH6, M, 256, 256);
    launch_gemm(EPI_SP, 0, PH6, sw[6], sb[6], nullptr, PH7, M, 256, 256);
    launch_gemm(EPI_SP, 0, PH7, sw[7], sb[7], nullptr, PB0, M, 256, 256);
    launch_gemm(EPI_LIN, 0, PB0, sw[8], sb[8], nullptr, PO8, M, 257, 256);

    // ---- backward (VJP of sdf channel w.r.t. points) ----
    k_bwinit<<<(M*256+255)/256, 256>>>(PB0, sw[8], PB1, M);
    launch_gemm(EPI_MASK, 1, PB1, sw[7], nullptr, PH7, PB0, M, 256, 256);
    launch_gemm(EPI_MASK, 1, PB0, sw[6], nullptr, PH6, PB1, M, 256, 256);
    launch_gemm(EPI_MASK, 1, PB1, sw[5], nullptr, PH5, PB0, M, 256, 256);
    launch_gemm(EPI_LIN,  1, PB0, sw[4], nullptr, nullptr, PB1, M, 256, 256);
    k_split<<<(M*256+255)/256, 256>>>(PB1, PH3, PB0, PGE, M);
    launch_gemm(EPI_MASK, 1, PB0, sw[3], nullptr, PH2, PB1, M, 256, 217);
    launch_gemm(EPI_MASK, 1, PB1, sw[2], nullptr, PH1, PB0, M, 256, 256);
    launch_gemm(EPI_MASK, 1, PB0, sw[1], nullptr, PH0, PB1, M, 256, 256);
    launch_gemm(EPI_LIN,  1, PB1, sw[0], nullptr, nullptr, PB0, M, 39, 256);
    k_gradpts<<<(M+255)/256, 256>>>(PB0, PGE, PP, PGR, M);

    // ---- color net + compositing ----
    k_alpha<<<(M+255)/256, 256>>>(PO8, PGR, PD, rd, var, PA, M);
    k_ray_weights<<<4, 256>>>(PA, PW);
    k_cin<<<(M*265+255)/256, 256>>>(PP, rd, PGR, PO8, PB0, M);
    launch_gemm(EPI_RELU, 0, PB0, cw[0], cb[0], nullptr, PB1, M, 256, 265);
    launch_gemm(EPI_RELU, 0, PB1, cw[1], cb[1], nullptr, PB0, M, 256, 256);
    k_color_head<<<(M*32+255)/256, 256>>>(PB0, cw[2], cb[2], PRGB, M);
    k_reduce<<<4, 256>>>(PW, PRGB, out);
}